// round 5
// baseline (speedup 1.0000x reference)
#include <cuda_runtime.h>
#include <math.h>

#define N_NODES 50000
#define N_EDGES 800000
#define DIN     256
#define H       384
#define NLAYERS 6
#define NCLS    2
#define EPSV    1e-5f

// ---------------- scratch (static device memory; no allocations) ----------------
__device__ float g_h   [(size_t)N_NODES * H];
__device__ float g_agg [(size_t)N_NODES * H];
__device__ float g_tmp [(size_t)N_NODES * H];
__device__ float g_stats[2 * H];          // col sums, col sums of squares
__device__ float g_bna [H];               // fused BN scale
__device__ float g_bnc [H];               // fused BN shift
__device__ float g_invcnt[N_NODES];
__device__ int   g_deg   [N_NODES];
__device__ int   g_colptr[N_NODES + 1];
__device__ int   g_cursor[N_NODES];
__device__ int   g_src   [N_EDGES];

// ---------------- CSR build ----------------
__global__ void hist_kernel(const int* __restrict__ col) {
    int i = blockIdx.x * blockDim.x + threadIdx.x;
    if (i < N_EDGES) atomicAdd(&g_deg[col[i]], 1);
}

// single-block inclusive-scan based exclusive prefix sum over N_NODES degrees
__global__ void scan_kernel() {
    __shared__ int buf[1024];
    int tid = threadIdx.x;
    int offset = 0;
    for (int base = 0; base < N_NODES; base += 1024) {
        int idx = base + tid;
        int v = (idx < N_NODES) ? g_deg[idx] : 0;
        buf[tid] = v;
        __syncthreads();
        for (int s = 1; s < 1024; s <<= 1) {
            int t = (tid >= s) ? buf[tid - s] : 0;
            __syncthreads();
            buf[tid] += t;
            __syncthreads();
        }
        if (idx < N_NODES) g_colptr[idx] = offset + buf[tid] - v;
        int tot = buf[1023];
        __syncthreads();      // protect buf[1023] read before next-iter overwrite
        offset += tot;
    }
    if (tid == 0) g_colptr[N_NODES] = offset;
}

__global__ void fill_kernel(const int* __restrict__ row, const int* __restrict__ col) {
    int i = blockIdx.x * blockDim.x + threadIdx.x;
    if (i < N_EDGES) {
        int p = atomicAdd(&g_cursor[col[i]], 1);
        g_src[p] = row[i];
    }
}

__global__ void invcnt_kernel() {
    int i = blockIdx.x * blockDim.x + threadIdx.x;
    if (i < N_NODES) g_invcnt[i] = 1.0f / fmaxf((float)g_deg[i], 1.0f);
}

// ---------------- mean aggregation: one warp per destination node ----------------
__global__ void agg_kernel(const float* __restrict__ h, float* __restrict__ out) {
    int w    = (blockIdx.x * blockDim.x + threadIdx.x) >> 5;
    int lane = threadIdx.x & 31;
    if (w >= N_NODES) return;
    int beg = g_colptr[w], end = g_colptr[w + 1];
    float4 a0 = make_float4(0.f, 0.f, 0.f, 0.f);
    float4 a1 = a0, a2 = a0;
    for (int e = beg; e < end; e++) {
        const float4* hp = (const float4*)(h + (size_t)g_src[e] * H);
        float4 v0 = hp[lane];
        float4 v1 = hp[lane + 32];
        float4 v2 = hp[lane + 64];
        a0.x += v0.x; a0.y += v0.y; a0.z += v0.z; a0.w += v0.w;
        a1.x += v1.x; a1.y += v1.y; a1.z += v1.z; a1.w += v1.w;
        a2.x += v2.x; a2.y += v2.y; a2.z += v2.z; a2.w += v2.w;
    }
    float s = g_invcnt[w];
    float4* op = (float4*)(out + (size_t)w * H);
    op[lane]      = make_float4(a0.x * s, a0.y * s, a0.z * s, a0.w * s);
    op[lane + 32] = make_float4(a1.x * s, a1.y * s, a1.z * s, a1.w * s);
    op[lane + 64] = make_float4(a2.x * s, a2.y * s, a2.z * s, a2.w * s);
}

// ---------------- fp32 tiled GEMM: C[M,Nc] (+)= A[M,K] @ B[K,Nc] ----------------
// BM=BN=128, BK=16, 256 threads, 8x8 per-thread register tile.
// flags: 1 = add bias, 2 = accumulate into C, 4 = relu
__global__ void __launch_bounds__(256) gemm_kernel(
    const float* __restrict__ A, const float* __restrict__ B,
    const float* __restrict__ bias, float* __restrict__ C,
    int M, int Nc, int K, int flags)
{
    __shared__ float As[16][128];
    __shared__ float Bs[16][128];
    const int tid = threadIdx.x;
    const int m0 = blockIdx.y * 128;
    const int n0 = blockIdx.x * 128;

    const int la_k = tid & 15;      // A tile: k index
    const int la_m = tid >> 4;      // A tile: m base (16 threads span, x8)
    const int lb_n = tid & 127;     // B tile: n index
    const int lb_k = tid >> 7;      // B tile: k base (2 values, x8)

    const int tx = tid & 15;        // col group (8 cols)
    const int ty = tid >> 4;        // row group (8 rows)

    float acc[8][8];
#pragma unroll
    for (int i = 0; i < 8; i++)
#pragma unroll
        for (int j = 0; j < 8; j++) acc[i][j] = 0.f;

    for (int kk = 0; kk < K; kk += 16) {
#pragma unroll
        for (int j = 0; j < 8; j++) {
            int m = la_m + j * 16;
            int gr = m0 + m;
            float v = 0.f;
            if (gr < M) v = A[(size_t)gr * K + kk + la_k];
            As[la_k][m] = v;
        }
#pragma unroll
        for (int j = 0; j < 8; j++) {
            int k = lb_k + j * 2;
            int gc = n0 + lb_n;
            float v = 0.f;
            if (gc < Nc) v = B[(size_t)(kk + k) * Nc + gc];
            Bs[k][lb_n] = v;
        }
        __syncthreads();
#pragma unroll
        for (int k = 0; k < 16; k++) {
            float4 a0 = *(const float4*)&As[k][ty * 8];
            float4 a1 = *(const float4*)&As[k][ty * 8 + 4];
            float4 b0 = *(const float4*)&Bs[k][tx * 8];
            float4 b1 = *(const float4*)&Bs[k][tx * 8 + 4];
            float av[8] = {a0.x, a0.y, a0.z, a0.w, a1.x, a1.y, a1.z, a1.w};
            float bv[8] = {b0.x, b0.y, b0.z, b0.w, b1.x, b1.y, b1.z, b1.w};
#pragma unroll
            for (int i = 0; i < 8; i++)
#pragma unroll
                for (int j = 0; j < 8; j++)
                    acc[i][j] = fmaf(av[i], bv[j], acc[i][j]);
        }
        __syncthreads();
    }

#pragma unroll
    for (int i = 0; i < 8; i++) {
        int r = m0 + ty * 8 + i;
        if (r < M) {
#pragma unroll
            for (int j = 0; j < 8; j++) {
                int c = n0 + tx * 8 + j;
                if (c < Nc) {
                    float v = acc[i][j];
                    if (flags & 1) v += bias[c];
                    if (flags & 2) v += C[(size_t)r * Nc + c];
                    if (flags & 4) v = fmaxf(v, 0.f);
                    C[(size_t)r * Nc + c] = v;
                }
            }
        }
    }
}

// ---------------- batchnorm ----------------
__global__ void bn_stats_kernel(const float* __restrict__ h) {
    int c = threadIdx.x;   // blockDim == H
    float s = 0.f, s2 = 0.f;
    for (int r = blockIdx.x; r < N_NODES; r += gridDim.x) {
        float v = h[(size_t)r * H + c];
        s += v; s2 += v * v;
    }
    atomicAdd(&g_stats[c], s);
    atomicAdd(&g_stats[H + c], s2);
}

__global__ void bn_final_kernel(const float* __restrict__ g, const float* __restrict__ b) {
    int c = threadIdx.x;
    if (c < H) {
        float inv = 1.0f / (float)N_NODES;
        float mu  = g_stats[c] * inv;
        float var = g_stats[H + c] * inv - mu * mu;
        float rs  = rsqrtf(var + EPSV);
        float a   = g[c] * rs;
        g_bna[c] = a;
        g_bnc[c] = b[c] - mu * a;
    }
}

__global__ void bn_apply_relu_kernel(float* __restrict__ h) {
    int i = blockIdx.x * blockDim.x + threadIdx.x;    // float4 index
    const int total = N_NODES * H / 4;
    if (i >= total) return;
    int c4 = i % (H / 4);
    float4 v = ((float4*)h)[i];
    float4 a = ((const float4*)g_bna)[c4];
    float4 c = ((const float4*)g_bnc)[c4];
    v.x = fmaxf(fmaf(v.x, a.x, c.x), 0.f);
    v.y = fmaxf(fmaf(v.y, a.y, c.y), 0.f);
    v.z = fmaxf(fmaf(v.z, a.z, c.z), 0.f);
    v.w = fmaxf(fmaf(v.w, a.w, c.w), 0.f);
    ((float4*)h)[i] = v;
}

// ---------------- final tiny GEMM: [N,96] @ [96,2] + b ----------------
__global__ void head3_kernel(const float* __restrict__ t2, const float* __restrict__ W3,
                             const float* __restrict__ b3, float* __restrict__ out) {
    __shared__ float w[96 * 2];
    __shared__ float bb[2];
    if (threadIdx.x < 192) w[threadIdx.x] = W3[threadIdx.x];
    if (threadIdx.x < 2)   bb[threadIdx.x] = b3[threadIdx.x];
    __syncthreads();
    int r = blockIdx.x * blockDim.x + threadIdx.x;
    if (r >= N_NODES) return;
    float a0 = bb[0], a1 = bb[1];
    const float* row = t2 + (size_t)r * 96;
#pragma unroll 8
    for (int k = 0; k < 96; k++) {
        float v = row[k];
        a0 = fmaf(v, w[k * 2],     a0);
        a1 = fmaf(v, w[k * 2 + 1], a1);
    }
    out[r * 2]     = a0;
    out[r * 2 + 1] = a1;
}

// ---------------- host orchestration ----------------
static void run_gemm(const float* A, const float* B, const float* bias, float* C,
                     int M, int Nc, int K, int flags) {
    dim3 grid((Nc + 127) / 128, (M + 127) / 128);
    gemm_kernel<<<grid, 256>>>(A, B, bias, C, M, Nc, K, flags);
}

extern "C" void kernel_launch(void* const* d_in, const int* in_sizes, int n_in,
                              void* d_out, int out_size) {
    const float* x     = (const float*)d_in[0];
    const int*   ei    = (const int*)  d_in[1];
    const float* W_in  = (const float*)d_in[2];
    const float* b_in  = (const float*)d_in[3];
    const float* bn0_g = (const float*)d_in[4];
    const float* bn0_b = (const float*)d_in[5];
    const float* Wl    = (const float*)d_in[6];
    const float* bl    = (const float*)d_in[7];
    const float* Wr    = (const float*)d_in[8];
    const float* bn_g  = (const float*)d_in[9];
    const float* bn_b  = (const float*)d_in[10];
    const float* Wskip = (const float*)d_in[11];
    const float* bskip = (const float*)d_in[12];
    const float* W1    = (const float*)d_in[13];
    const float* b1    = (const float*)d_in[14];
    const float* W2    = (const float*)d_in[15];
    const float* b2    = (const float*)d_in[16];
    const float* W3    = (const float*)d_in[17];
    const float* b3    = (const float*)d_in[18];

    float* logits_out = (float*)d_out;
    float* emb_out    = logits_out + (size_t)N_NODES * NCLS;

    float *h, *agg, *tmp, *stats;
    int *deg, *colptr, *cursor;
    cudaGetSymbolAddress((void**)&h,      g_h);
    cudaGetSymbolAddress((void**)&agg,    g_agg);
    cudaGetSymbolAddress((void**)&tmp,    g_tmp);
    cudaGetSymbolAddress((void**)&stats,  g_stats);
    cudaGetSymbolAddress((void**)&deg,    g_deg);
    cudaGetSymbolAddress((void**)&colptr, g_colptr);
    cudaGetSymbolAddress((void**)&cursor, g_cursor);

    const int* e_row = ei;
    const int* e_col = ei + N_EDGES;

    // ---- CSR build (per launch; deterministic work) ----
    cudaMemsetAsync(deg, 0, N_NODES * sizeof(int));
    hist_kernel<<<(N_EDGES + 255) / 256, 256>>>(e_col);
    scan_kernel<<<1, 1024>>>();
    cudaMemcpyAsync(cursor, colptr, N_NODES * sizeof(int), cudaMemcpyDeviceToDevice);
    fill_kernel<<<(N_EDGES + 255) / 256, 256>>>(e_row, e_col);
    invcnt_kernel<<<(N_NODES + 255) / 256, 256>>>();

    // ---- input layer: h = relu(bn0(x @ W_in + b_in)) ----
    run_gemm(x, W_in, b_in, h, N_NODES, H, DIN, /*bias*/1);
    cudaMemsetAsync(stats, 0, 2 * H * sizeof(float));
    bn_stats_kernel<<<256, H>>>(h);
    bn_final_kernel<<<1, H>>>(bn0_g, bn0_b);
    {
        int total4 = N_NODES * H / 4;
        bn_apply_relu_kernel<<<(total4 + 255) / 256, 256>>>(h);
    }

    // ---- SAGE layers ----
    int skip = 0;
    for (int i = 0; i < NLAYERS; i++) {
        agg_kernel<<<(N_NODES * 32 + 255) / 256, 256>>>(h, agg);
        run_gemm(agg, Wl + (size_t)i * H * H, bl + (size_t)i * H, tmp, N_NODES, H, H, /*bias*/1);
        run_gemm(h,   Wr + (size_t)i * H * H, nullptr,            tmp, N_NODES, H, H, /*acc*/2);
        cudaMemsetAsync(stats, 0, 2 * H * sizeof(float));
        bn_stats_kernel<<<256, H>>>(tmp);
        bn_final_kernel<<<1, H>>>(bn_g + (size_t)i * H, bn_b + (size_t)i * H);
        {
            int total4 = N_NODES * H / 4;
            bn_apply_relu_kernel<<<(total4 + 255) / 256, 256>>>(tmp);
        }
        if ((i & 1) == 1) {   // (i+1) % 2 == 0
            run_gemm(h, Wskip + (size_t)skip * H * H, bskip + (size_t)skip * H,
                     tmp, N_NODES, H, H, /*bias|acc*/3);
            skip++;
        }
        float* t = h; h = tmp; tmp = t;
    }

    // ---- outputs: embeddings + MLP head ----
    cudaMemcpyAsync(emb_out, h, (size_t)N_NODES * H * sizeof(float),
                    cudaMemcpyDeviceToDevice);
    run_gemm(h,   W1, b1, agg, N_NODES, H / 2, H,     /*bias|relu*/5);   // t1: [N,192]
    run_gemm(agg, W2, b2, tmp, N_NODES, H / 4, H / 2, /*bias|relu*/5);   // t2: [N,96]
    head3_kernel<<<(N_NODES + 255) / 256, 256>>>(tmp, W3, b3, logits_out);
}

// round 6
// speedup vs baseline: 2.4552x; 2.4552x over previous
#include <cuda_runtime.h>
#include <cuda_bf16.h>
#include <math.h>
#include <stdint.h>

#define N_NODES 50000
#define N_EDGES 800000
#define DIN     256
#define H       384
#define NLAYERS 6
#define NCLS    2
#define EPSV    1e-5f

typedef __nv_bfloat16 bf16;

// ---------------- fp32 scratch ----------------
__device__ float g_h   [(size_t)N_NODES * H];
__device__ float g_tmp [(size_t)N_NODES * H];
__device__ float g_t1f [(size_t)N_NODES * H];   // head t1 fp32 scratch
__device__ float g_stats[2 * H];
__device__ float g_bna [H];
__device__ float g_bnc [H];
__device__ float g_invcnt[N_NODES];
__device__ int   g_deg   [N_NODES];
__device__ int   g_colptr[N_NODES + 1];
__device__ int   g_cursor[N_NODES];
__device__ int   g_src   [N_EDGES];

// ---------------- bf16 split scratch (one big arena) ----------------
#define NH ((size_t)N_NODES * H)                 // 19,200,000
static const size_t OFF_HSA_H = 0;
static const size_t OFF_HSA_L = 1 * NH;
static const size_t OFF_HSB_H = 2 * NH;
static const size_t OFF_HSB_L = 3 * NH;
static const size_t OFF_AGG_H = 4 * NH;
static const size_t OFF_AGG_L = 5 * NH;
static const size_t OFF_X_H   = 6 * NH;          // N*DIN used
static const size_t OFF_X_L   = 7 * NH;
static const size_t OFF_T1_H  = 8 * NH;          // N*192 used
static const size_t OFF_T1_L  = 9 * NH;
static const size_t SZ_WIN = (size_t)DIN * H;                 // 98304
static const size_t SZ_WL  = (size_t)NLAYERS * H * H;         // 884736*... 6*147456=884736? (6*384*384=884736)
static const size_t SZ_WSK = (size_t)(NLAYERS / 2) * H * H;
static const size_t SZ_W1  = (size_t)H * (H / 2);
static const size_t SZ_W2  = (size_t)(H / 2) * (H / 4);
static const size_t OFF_WIN_H = 10 * NH;
static const size_t OFF_WIN_L = OFF_WIN_H + SZ_WIN;
static const size_t OFF_WL_H  = OFF_WIN_L + SZ_WIN;
static const size_t OFF_WL_L  = OFF_WL_H + SZ_WL;
static const size_t OFF_WR_H  = OFF_WL_L + SZ_WL;
static const size_t OFF_WR_L  = OFF_WR_H + SZ_WL;
static const size_t OFF_WSK_H = OFF_WR_L + SZ_WL;
static const size_t OFF_WSK_L = OFF_WSK_H + SZ_WSK;
static const size_t OFF_W1_H  = OFF_WSK_L + SZ_WSK;
static const size_t OFF_W1_L  = OFF_W1_H + SZ_W1;
static const size_t OFF_W2_H  = OFF_W1_L + SZ_W1;
static const size_t OFF_W2_L  = OFF_W2_H + SZ_W2;
static const size_t BF_TOTAL  = OFF_W2_L + SZ_W2;

__device__ bf16 g_bf[BF_TOTAL];

// ---------------- CSR build ----------------
__global__ void hist_kernel(const int* __restrict__ col) {
    int i = blockIdx.x * blockDim.x + threadIdx.x;
    if (i < N_EDGES) atomicAdd(&g_deg[col[i]], 1);
}

__global__ void scan_kernel() {
    __shared__ int buf[1024];
    int tid = threadIdx.x;
    int offset = 0;
    for (int base = 0; base < N_NODES; base += 1024) {
        int idx = base + tid;
        int v = (idx < N_NODES) ? g_deg[idx] : 0;
        buf[tid] = v;
        __syncthreads();
        for (int s = 1; s < 1024; s <<= 1) {
            int t = (tid >= s) ? buf[tid - s] : 0;
            __syncthreads();
            buf[tid] += t;
            __syncthreads();
        }
        if (idx < N_NODES) g_colptr[idx] = offset + buf[tid] - v;
        int tot = buf[1023];
        __syncthreads();
        offset += tot;
    }
    if (tid == 0) g_colptr[N_NODES] = offset;
}

__global__ void fill_kernel(const int* __restrict__ row, const int* __restrict__ col) {
    int i = blockIdx.x * blockDim.x + threadIdx.x;
    if (i < N_EDGES) {
        int p = atomicAdd(&g_cursor[col[i]], 1);
        g_src[p] = row[i];
    }
}

__global__ void invcnt_kernel() {
    int i = blockIdx.x * blockDim.x + threadIdx.x;
    if (i < N_NODES) g_invcnt[i] = 1.0f / fmaxf((float)g_deg[i], 1.0f);
}

// ---------------- generic fp32 -> (bf16 hi, bf16 lo) split ----------------
__global__ void split_kernel(const float* __restrict__ src,
                             bf16* __restrict__ hi, bf16* __restrict__ lo, int n) {
    int i = blockIdx.x * blockDim.x + threadIdx.x;
    if (i < n) {
        float v = src[i];
        bf16 h = __float2bfloat16(v);
        hi[i] = h;
        lo[i] = __float2bfloat16(v - __bfloat162float(h));
    }
}

// ---------------- mean aggregation: one warp per node, outputs bf16 splits ----------------
__global__ void agg_kernel(const float* __restrict__ h,
                           bf16* __restrict__ ohi, bf16* __restrict__ olo) {
    int w    = (blockIdx.x * blockDim.x + threadIdx.x) >> 5;
    int lane = threadIdx.x & 31;
    if (w >= N_NODES) return;
    int beg = g_colptr[w], end = g_colptr[w + 1];
    float4 a0 = make_float4(0.f, 0.f, 0.f, 0.f);
    float4 a1 = a0, a2 = a0;
    for (int e = beg; e < end; e++) {
        const float4* hp = (const float4*)(h + (size_t)g_src[e] * H);
        float4 v0 = hp[lane];
        float4 v1 = hp[lane + 32];
        float4 v2 = hp[lane + 64];
        a0.x += v0.x; a0.y += v0.y; a0.z += v0.z; a0.w += v0.w;
        a1.x += v1.x; a1.y += v1.y; a1.z += v1.z; a1.w += v1.w;
        a2.x += v2.x; a2.y += v2.y; a2.z += v2.z; a2.w += v2.w;
    }
    float s = g_invcnt[w];
    float vals[12] = {a0.x*s, a0.y*s, a0.z*s, a0.w*s,
                      a1.x*s, a1.y*s, a1.z*s, a1.w*s,
                      a2.x*s, a2.y*s, a2.z*s, a2.w*s};
    size_t base = (size_t)w * H + lane * 4;
#pragma unroll
    for (int g = 0; g < 3; g++) {
#pragma unroll
        for (int j = 0; j < 4; j++) {
            float v = vals[g * 4 + j];
            bf16 hb = __float2bfloat16(v);
            ohi[base + g * 128 + j] = hb;
            olo[base + g * 128 + j] = __float2bfloat16(v - __bfloat162float(hb));
        }
    }
}

// ---------------- mma helpers ----------------
__device__ __forceinline__ void ldsm_x4(uint32_t* r, const void* p) {
    uint32_t a = (uint32_t)__cvta_generic_to_shared(p);
    asm volatile("ldmatrix.sync.aligned.m8n8.x4.shared.b16 {%0,%1,%2,%3}, [%4];"
                 : "=r"(r[0]), "=r"(r[1]), "=r"(r[2]), "=r"(r[3]) : "r"(a));
}
__device__ __forceinline__ void ldsm_x2t(uint32_t* r, const void* p) {
    uint32_t a = (uint32_t)__cvta_generic_to_shared(p);
    asm volatile("ldmatrix.sync.aligned.m8n8.x2.trans.shared.b16 {%0,%1}, [%2];"
                 : "=r"(r[0]), "=r"(r[1]) : "r"(a));
}
__device__ __forceinline__ void mma16816(float* d, const uint32_t* a, const uint32_t* b) {
    asm volatile("mma.sync.aligned.m16n8k16.row.col.f32.bf16.bf16.f32 "
                 "{%0,%1,%2,%3}, {%4,%5,%6,%7}, {%8,%9}, {%0,%1,%2,%3};"
                 : "+f"(d[0]), "+f"(d[1]), "+f"(d[2]), "+f"(d[3])
                 : "r"(a[0]), "r"(a[1]), "r"(a[2]), "r"(a[3]), "r"(b[0]), "r"(b[1]));
}

// ---------------- bf16x3 tensor-core GEMM ----------------
// C[M,Nc] (+)= A1[M,K1]@B1[K1,Nc] (+ A2[M,K2]@B2[K2,Nc])
// Each operand given as (hi, lo) bf16 split; product = hi*hi + hi*lo + lo*hi.
// flags: 1 = +bias, 2 = accumulate existing C, 4 = relu.
// ohi/olo (optional): also store bf16 split of the result.
__global__ void __launch_bounds__(256) gemm_mma_kernel(
    const bf16* __restrict__ a1h, const bf16* __restrict__ a1l,
    const bf16* __restrict__ b1h, const bf16* __restrict__ b1l, int K1,
    const bf16* __restrict__ a2h, const bf16* __restrict__ a2l,
    const bf16* __restrict__ b2h, const bf16* __restrict__ b2l, int K2,
    const float* __restrict__ bias, float* __restrict__ C,
    bf16* __restrict__ ohi, bf16* __restrict__ olo,
    int M, int Nc, int flags)
{
    __shared__ bf16 Ah[128][40];
    __shared__ bf16 Al[128][40];
    __shared__ bf16 Bh[32][136];
    __shared__ bf16 Bl[32][136];

    const int tid  = threadIdx.x;
    const int lane = tid & 31;
    const int wid  = tid >> 5;
    const int wm   = (wid >> 2) * 64;
    const int wn   = (wid & 3) * 32;
    const int m0   = blockIdx.y * 128;
    const int n0   = blockIdx.x * 128;

    float acc[4][4][4];
#pragma unroll
    for (int i = 0; i < 4; i++)
#pragma unroll
        for (int j = 0; j < 4; j++)
#pragma unroll
            for (int k = 0; k < 4; k++) acc[i][j][k] = 0.f;

    for (int pass = 0; pass < 2; pass++) {
        if (pass == 1 && a2h == nullptr) break;
        const bf16* ah = pass ? a2h : a1h;
        const bf16* al = pass ? a2l : a1l;
        const bf16* bh = pass ? b2h : b1h;
        const bf16* bl = pass ? b2l : b1l;
        const int K = pass ? K2 : K1;

        for (int kk = 0; kk < K; kk += 32) {
            __syncthreads();
            // load A tiles (both splits): 128x32, uint4 = 8 bf16
#pragma unroll
            for (int i = 0; i < 2; i++) {
                int idx = i * 256 + tid;
                int r = idx >> 2, cg = idx & 3;
                uint4 vh = make_uint4(0, 0, 0, 0), vl = vh;
                int gr = m0 + r;
                if (gr < M) {
                    size_t off = (size_t)gr * K + kk + cg * 8;
                    vh = *(const uint4*)(ah + off);
                    vl = *(const uint4*)(al + off);
                }
                *(uint4*)&Ah[r][cg * 8] = vh;
                *(uint4*)&Al[r][cg * 8] = vl;
            }
            // load B tiles (both splits): 32x128
#pragma unroll
            for (int i = 0; i < 2; i++) {
                int idx = i * 256 + tid;
                int r = idx >> 4, cg = idx & 15;
                int gc = n0 + cg * 8;
                uint4 vh = make_uint4(0, 0, 0, 0), vl = vh;
                if (gc < Nc) {
                    size_t off = (size_t)(kk + r) * Nc + gc;
                    vh = *(const uint4*)(bh + off);
                    vl = *(const uint4*)(bl + off);
                }
                *(uint4*)&Bh[r][cg * 8] = vh;
                *(uint4*)&Bl[r][cg * 8] = vl;
            }
            __syncthreads();

#pragma unroll
            for (int ks = 0; ks < 2; ks++) {
#pragma unroll
                for (int s = 0; s < 3; s++) {
                    const bf16 (*As)[40]  = (s == 2) ? Al : Ah;
                    const bf16 (*Bs)[136] = (s == 1) ? Bl : Bh;
                    uint32_t af[4][4], bfr[4][2];
#pragma unroll
                    for (int mi = 0; mi < 4; mi++)
                        ldsm_x4(af[mi], &As[wm + mi * 16 + (lane & 15)][ks * 16 + (lane >> 4) * 8]);
#pragma unroll
                    for (int ni = 0; ni < 4; ni++)
                        ldsm_x2t(bfr[ni], &Bs[ks * 16 + (lane & 15)][wn + ni * 8]);
#pragma unroll
                    for (int mi = 0; mi < 4; mi++)
#pragma unroll
                        for (int ni = 0; ni < 4; ni++)
                            mma16816(acc[mi][ni], af[mi], bfr[ni]);
                }
            }
        }
    }

    // epilogue
#pragma unroll
    for (int mi = 0; mi < 4; mi++) {
#pragma unroll
        for (int ni = 0; ni < 4; ni++) {
            int rbase = m0 + wm + mi * 16 + (lane >> 2);
            int cbase = n0 + wn + ni * 8 + (lane & 3) * 2;
#pragma unroll
            for (int half = 0; half < 2; half++) {
                int r = rbase + half * 8;
                if (r < M) {
#pragma unroll
                    for (int j = 0; j < 2; j++) {
                        int c = cbase + j;
                        if (c < Nc) {
                            float v = acc[mi][ni][half * 2 + j];
                            if (flags & 1) v += bias[c];
                            if (flags & 2) v += C[(size_t)r * Nc + c];
                            if (flags & 4) v = fmaxf(v, 0.f);
                            C[(size_t)r * Nc + c] = v;
                            if (ohi) {
                                bf16 hv = __float2bfloat16(v);
                                ohi[(size_t)r * Nc + c] = hv;
                                olo[(size_t)r * Nc + c] =
                                    __float2bfloat16(v - __bfloat162float(hv));
                            }
                        }
                    }
                }
            }
        }
    }
}

// ---------------- batchnorm ----------------
__global__ void bn_stats_kernel(const float* __restrict__ h) {
    int c = threadIdx.x;
    float s = 0.f, s2 = 0.f;
    for (int r = blockIdx.x; r < N_NODES; r += gridDim.x) {
        float v = h[(size_t)r * H + c];
        s += v; s2 += v * v;
    }
    atomicAdd(&g_stats[c], s);
    atomicAdd(&g_stats[H + c], s2);
}

__global__ void bn_final_kernel(const float* __restrict__ g, const float* __restrict__ b) {
    int c = threadIdx.x;
    if (c < H) {
        float inv = 1.0f / (float)N_NODES;
        float mu  = g_stats[c] * inv;
        float var = g_stats[H + c] * inv - mu * mu;
        float rs  = rsqrtf(var + EPSV);
        float a   = g[c] * rs;
        g_bna[c] = a;
        g_bnc[c] = b[c] - mu * a;
    }
}

// BN affine + relu, optional bf16 split output
__global__ void bn_apply_relu_kernel(float* __restrict__ h,
                                     bf16* __restrict__ ohi, bf16* __restrict__ olo) {
    int i = blockIdx.x * blockDim.x + threadIdx.x;    // float4 index
    const int total = N_NODES * H / 4;
    if (i >= total) return;
    int c4 = i % (H / 4);
    float4 v = ((float4*)h)[i];
    float4 a = ((const float4*)g_bna)[c4];
    float4 c = ((const float4*)g_bnc)[c4];
    v.x = fmaxf(fmaf(v.x, a.x, c.x), 0.f);
    v.y = fmaxf(fmaf(v.y, a.y, c.y), 0.f);
    v.z = fmaxf(fmaf(v.z, a.z, c.z), 0.f);
    v.w = fmaxf(fmaf(v.w, a.w, c.w), 0.f);
    ((float4*)h)[i] = v;
    if (ohi) {
        size_t base = (size_t)i * 4;
        float vv[4] = {v.x, v.y, v.z, v.w};
        bf16 hb[4], lb[4];
#pragma unroll
        for (int j = 0; j < 4; j++) {
            hb[j] = __float2bfloat16(vv[j]);
            lb[j] = __float2bfloat16(vv[j] - __bfloat162float(hb[j]));
        }
        ((__nv_bfloat162*)(ohi + base))[0] = __halves2bfloat162(hb[0], hb[1]);
        ((__nv_bfloat162*)(ohi + base))[1] = __halves2bfloat162(hb[2], hb[3]);
        ((__nv_bfloat162*)(olo + base))[0] = __halves2bfloat162(lb[0], lb[1]);
        ((__nv_bfloat162*)(olo + base))[1] = __halves2bfloat162(lb[2], lb[3]);
    }
}

// ---------------- final tiny GEMM: [N,96] @ [96,2] + b ----------------
__global__ void head3_kernel(const float* __restrict__ t2, const float* __restrict__ W3,
                             const float* __restrict__ b3, float* __restrict__ out) {
    __shared__ float w[96 * 2];
    __shared__ float bb[2];
    if (threadIdx.x < 192) w[threadIdx.x] = W3[threadIdx.x];
    if (threadIdx.x < 2)   bb[threadIdx.x] = b3[threadIdx.x];
    __syncthreads();
    int r = blockIdx.x * blockDim.x + threadIdx.x;
    if (r >= N_NODES) return;
    float a0 = bb[0], a1 = bb[1];
    const float* row = t2 + (size_t)r * 96;
#pragma unroll 8
    for (int k = 0; k < 96; k++) {
        float v = row[k];
        a0 = fmaf(v, w[k * 2],     a0);
        a1 = fmaf(v, w[k * 2 + 1], a1);
    }
    out[r * 2]     = a0;
    out[r * 2 + 1] = a1;
}

// ---------------- host orchestration ----------------
static void run_split(const float* src, bf16* hi, bf16* lo, size_t n) {
    split_kernel<<<(int)((n + 255) / 256), 256>>>(src, hi, lo, (int)n);
}

static void run_gemm(const bf16* a1h, const bf16* a1l, const bf16* b1h, const bf16* b1l, int K1,
                     const bf16* a2h, const bf16* a2l, const bf16* b2h, const bf16* b2l, int K2,
                     const float* bias, float* C, bf16* ohi, bf16* olo,
                     int M, int Nc, int flags) {
    dim3 grid((Nc + 127) / 128, (M + 127) / 128);
    gemm_mma_kernel<<<grid, 256>>>(a1h, a1l, b1h, b1l, K1,
                                   a2h, a2l, b2h, b2l, K2,
                                   bias, C, ohi, olo, M, Nc, flags);
}

extern "C" void kernel_launch(void* const* d_in, const int* in_sizes, int n_in,
                              void* d_out, int out_size) {
    const float* x     = (const float*)d_in[0];
    const int*   ei    = (const int*)  d_in[1];
    const float* W_in  = (const float*)d_in[2];
    const float* b_in  = (const float*)d_in[3];
    const float* bn0_g = (const float*)d_in[4];
    const float* bn0_b = (const float*)d_in[5];
    const float* Wl    = (const float*)d_in[6];
    const float* bl    = (const float*)d_in[7];
    const float* Wr    = (const float*)d_in[8];
    const float* bn_g  = (const float*)d_in[9];
    const float* bn_b  = (const float*)d_in[10];
    const float* Wskip = (const float*)d_in[11];
    const float* bskip = (const float*)d_in[12];
    const float* W1    = (const float*)d_in[13];
    const float* b1    = (const float*)d_in[14];
    const float* W2    = (const float*)d_in[15];
    const float* b2    = (const float*)d_in[16];
    const float* W3    = (const float*)d_in[17];
    const float* b3    = (const float*)d_in[18];

    float* logits_out = (float*)d_out;
    float* emb_out    = logits_out + (size_t)N_NODES * NCLS;

    float *hf, *tf, *t1f, *stats;
    int *deg, *colptr, *cursor;
    bf16* bfb;
    cudaGetSymbolAddress((void**)&hf,     g_h);
    cudaGetSymbolAddress((void**)&tf,     g_tmp);
    cudaGetSymbolAddress((void**)&t1f,    g_t1f);
    cudaGetSymbolAddress((void**)&stats,  g_stats);
    cudaGetSymbolAddress((void**)&deg,    g_deg);
    cudaGetSymbolAddress((void**)&colptr, g_colptr);
    cudaGetSymbolAddress((void**)&cursor, g_cursor);
    cudaGetSymbolAddress((void**)&bfb,    g_bf);

    bf16 *hsH = bfb + OFF_HSA_H, *hsL = bfb + OFF_HSA_L;   // splits of hf
    bf16 *tsH = bfb + OFF_HSB_H, *tsL = bfb + OFF_HSB_L;   // splits of tf
    bf16 *agH = bfb + OFF_AGG_H, *agL = bfb + OFF_AGG_L;
    bf16 *xH  = bfb + OFF_X_H,   *xL  = bfb + OFF_X_L;
    bf16 *t1H = bfb + OFF_T1_H,  *t1L = bfb + OFF_T1_L;
    bf16 *WinH = bfb + OFF_WIN_H, *WinL = bfb + OFF_WIN_L;
    bf16 *WlH  = bfb + OFF_WL_H,  *WlL  = bfb + OFF_WL_L;
    bf16 *WrH  = bfb + OFF_WR_H,  *WrL  = bfb + OFF_WR_L;
    bf16 *WskH = bfb + OFF_WSK_H, *WskL = bfb + OFF_WSK_L;
    bf16 *W1H  = bfb + OFF_W1_H,  *W1L  = bfb + OFF_W1_L;
    bf16 *W2H  = bfb + OFF_W2_H,  *W2L  = bfb + OFF_W2_L;

    const int* e_row = ei;
    const int* e_col = ei + N_EDGES;

    // ---- CSR build ----
    cudaMemsetAsync(deg, 0, N_NODES * sizeof(int));
    hist_kernel<<<(N_EDGES + 255) / 256, 256>>>(e_col);
    scan_kernel<<<1, 1024>>>();
    cudaMemcpyAsync(cursor, colptr, N_NODES * sizeof(int), cudaMemcpyDeviceToDevice);
    fill_kernel<<<(N_EDGES + 255) / 256, 256>>>(e_row, e_col);
    invcnt_kernel<<<(N_NODES + 255) / 256, 256>>>();

    // ---- split weights + x into bf16 hi/lo ----
    run_split(W_in,  WinH, WinL, SZ_WIN);
    run_split(Wl,    WlH,  WlL,  SZ_WL);
    run_split(Wr,    WrH,  WrL,  SZ_WL);
    run_split(Wskip, WskH, WskL, SZ_WSK);
    run_split(W1,    W1H,  W1L,  SZ_W1);
    run_split(W2,    W2H,  W2L,  SZ_W2);
    run_split(x,     xH,   xL,   (size_t)N_NODES * DIN);

    // ---- input layer: h = relu(bn0(x @ W_in + b_in)) ----
    run_gemm(xH, xL, WinH, WinL, DIN,
             nullptr, nullptr, nullptr, nullptr, 0,
             b_in, hf, nullptr, nullptr, N_NODES, H, /*bias*/1);
    cudaMemsetAsync(stats, 0, 2 * H * sizeof(float));
    bn_stats_kernel<<<256, H>>>(hf);
    bn_final_kernel<<<1, H>>>(bn0_g, bn0_b);
    {
        int total4 = N_NODES * H / 4;
        bn_apply_relu_kernel<<<(total4 + 255) / 256, 256>>>(hf, hsH, hsL);
    }

    // ---- SAGE layers ----
    int skip = 0;
    for (int i = 0; i < NLAYERS; i++) {
        bool is_skip = ((i & 1) == 1);
        // mean aggregation of current h -> bf16 splits
        agg_kernel<<<(N_NODES * 32 + 255) / 256, 256>>>(hf, agH, agL);
        // tmp = agg@Wl[i] + bl[i] + h@Wr[i]   (fused 2-pass GEMM)
        run_gemm(agH, agL, WlH + (size_t)i * H * H, WlL + (size_t)i * H * H, H,
                 hsH, hsL, WrH + (size_t)i * H * H, WrL + (size_t)i * H * H, H,
                 bl + (size_t)i * H, tf, nullptr, nullptr, N_NODES, H, /*bias*/1);
        // batchnorm + relu
        cudaMemsetAsync(stats, 0, 2 * H * sizeof(float));
        bn_stats_kernel<<<256, H>>>(tf);
        bn_final_kernel<<<1, H>>>(bn_g + (size_t)i * H, bn_b + (size_t)i * H);
        {
            int total4 = N_NODES * H / 4;
            bn_apply_relu_kernel<<<(total4 + 255) / 256, 256>>>(
                tf, is_skip ? nullptr : tsH, is_skip ? nullptr : tsL);
        }
        if (is_skip) {
            // tmp += identity @ Wskip + bskip ; split of result -> ts
            run_gemm(hsH, hsL, WskH + (size_t)skip * H * H, WskL + (size_t)skip * H * H, H,
                     nullptr, nullptr, nullptr, nullptr, 0,
                     bskip + (size_t)skip * H, tf, tsH, tsL, N_NODES, H, /*bias|acc*/3);
            skip++;
        }
        // swap fp32 buffers and their split buffers together
        float* ft = hf; hf = tf; tf = ft;
        bf16* bt;
        bt = hsH; hsH = tsH; tsH = bt;
        bt = hsL; hsL = tsL; tsL = bt;
    }

    // ---- outputs: embeddings + MLP head ----
    cudaMemcpyAsync(emb_out, hf, (size_t)N_NODES * H * sizeof(float),
                    cudaMemcpyDeviceToDevice);
    // t1 = relu(h@W1 + b1), split out
    run_gemm(hsH, hsL, W1H, W1L, H,
             nullptr, nullptr, nullptr, nullptr, 0,
             b1, t1f, t1H, t1L, N_NODES, H / 2, /*bias|relu*/5);
    // t2 = relu(t1@W2 + b2) -> tf (fp32)
    run_gemm(t1H, t1L, W2H, W2L, H / 2,
             nullptr, nullptr, nullptr, nullptr, 0,
             b2, tf, nullptr, nullptr, N_NODES, H / 4, /*bias|relu*/5);
    // logits
    head3_kernel<<<(N_NODES + 255) / 256, 256>>>(tf, W3, b3, logits_out);
}

// round 9
// speedup vs baseline: 2.6126x; 1.0641x over previous
#include <cuda_runtime.h>
#include <cuda_bf16.h>
#include <math.h>
#include <stdint.h>

#define N_NODES 50000
#define N_EDGES 800000
#define DIN     256
#define H       384
#define NLAYERS 6
#define NCLS    2
#define EPSV    1e-5f

typedef __nv_bfloat16 bf16;

// ---------------- fp32 scratch ----------------
__device__ float g_h   [(size_t)N_NODES * H];
__device__ float g_tmp [(size_t)N_NODES * H];
__device__ float g_t1f [(size_t)N_NODES * H];
__device__ float g_stats[2 * H];
__device__ float g_bna [H];
__device__ float g_bnc [H];
__device__ float g_invcnt[N_NODES];
__device__ int   g_deg   [N_NODES];
__device__ int   g_colptr[N_NODES + 1];
__device__ int   g_cursor[N_NODES];
__device__ int   g_src   [N_EDGES];

// ---------------- bf16 split scratch ----------------
#define NH ((size_t)N_NODES * H)
static const size_t OFF_HSA_H = 0;
static const size_t OFF_HSA_L = 1 * NH;
static const size_t OFF_HSB_H = 2 * NH;
static const size_t OFF_HSB_L = 3 * NH;
static const size_t OFF_AGG_H = 4 * NH;
static const size_t OFF_AGG_L = 5 * NH;
static const size_t OFF_X_H   = 6 * NH;
static const size_t OFF_X_L   = 7 * NH;
static const size_t OFF_T1_H  = 8 * NH;
static const size_t OFF_T1_L  = 9 * NH;
static const size_t SZ_WIN = (size_t)DIN * H;
static const size_t SZ_WL  = (size_t)NLAYERS * H * H;
static const size_t SZ_WSK = (size_t)(NLAYERS / 2) * H * H;
static const size_t SZ_W1  = (size_t)H * (H / 2);
static const size_t SZ_W2  = (size_t)(H / 2) * (H / 4);
static const size_t OFF_WIN_H = 10 * NH;
static const size_t OFF_WIN_L = OFF_WIN_H + SZ_WIN;
static const size_t OFF_WL_H  = OFF_WIN_L + SZ_WIN;
static const size_t OFF_WL_L  = OFF_WL_H + SZ_WL;
static const size_t OFF_WR_H  = OFF_WL_L + SZ_WL;
static const size_t OFF_WR_L  = OFF_WR_H + SZ_WL;
static const size_t OFF_WSK_H = OFF_WR_L + SZ_WL;
static const size_t OFF_WSK_L = OFF_WSK_H + SZ_WSK;
static const size_t OFF_W1_H  = OFF_WSK_L + SZ_WSK;
static const size_t OFF_W1_L  = OFF_W1_H + SZ_W1;
static const size_t OFF_W2_H  = OFF_W1_L + SZ_W1;
static const size_t OFF_W2_L  = OFF_W2_H + SZ_W2;
static const size_t BF_TOTAL  = OFF_W2_L + SZ_W2;

__device__ bf16 g_bf[BF_TOTAL];

// ---------------- CSR build ----------------
__global__ void hist_kernel(const int* __restrict__ col) {
    int i = blockIdx.x * blockDim.x + threadIdx.x;
    if (i < N_EDGES) atomicAdd(&g_deg[col[i]], 1);
}

__global__ void scan_kernel() {
    __shared__ int buf[1024];
    int tid = threadIdx.x;
    int offset = 0;
    for (int base = 0; base < N_NODES; base += 1024) {
        int idx = base + tid;
        int v = (idx < N_NODES) ? g_deg[idx] : 0;
        buf[tid] = v;
        __syncthreads();
        for (int s = 1; s < 1024; s <<= 1) {
            int t = (tid >= s) ? buf[tid - s] : 0;
            __syncthreads();
            buf[tid] += t;
            __syncthreads();
        }
        if (idx < N_NODES) g_colptr[idx] = offset + buf[tid] - v;
        int tot = buf[1023];
        __syncthreads();
        offset += tot;
    }
    if (tid == 0) g_colptr[N_NODES] = offset;
}

__global__ void fill_kernel(const int* __restrict__ row, const int* __restrict__ col) {
    int i = blockIdx.x * blockDim.x + threadIdx.x;
    if (i < N_EDGES) {
        int p = atomicAdd(&g_cursor[col[i]], 1);
        g_src[p] = row[i];
    }
}

__global__ void invcnt_kernel() {
    int i = blockIdx.x * blockDim.x + threadIdx.x;
    if (i < N_NODES) g_invcnt[i] = 1.0f / fmaxf((float)g_deg[i], 1.0f);
}

// ---------------- splits ----------------
__global__ void split_kernel(const float* __restrict__ src,
                             bf16* __restrict__ hi, bf16* __restrict__ lo, int n) {
    int i = blockIdx.x * blockDim.x + threadIdx.x;
    if (i < n) {
        float v = src[i];
        bf16 h = __float2bfloat16(v);
        hi[i] = h;
        lo[i] = __float2bfloat16(v - __bfloat162float(h));
    }
}

// ---------------- mean aggregation ----------------
__global__ void agg_kernel(const float* __restrict__ h,
                           bf16* __restrict__ ohi, bf16* __restrict__ olo) {
    int w    = (blockIdx.x * blockDim.x + threadIdx.x) >> 5;
    int lane = threadIdx.x & 31;
    if (w >= N_NODES) return;
    int beg = g_colptr[w], end = g_colptr[w + 1];
    float4 a0 = make_float4(0.f, 0.f, 0.f, 0.f);
    float4 a1 = a0, a2 = a0;
    for (int e = beg; e < end; e++) {
        const float4* hp = (const float4*)(h + (size_t)g_src[e] * H);
        float4 v0 = hp[lane];
        float4 v1 = hp[lane + 32];
        float4 v2 = hp[lane + 64];
        a0.x += v0.x; a0.y += v0.y; a0.z += v0.z; a0.w += v0.w;
        a1.x += v1.x; a1.y += v1.y; a1.z += v1.z; a1.w += v1.w;
        a2.x += v2.x; a2.y += v2.y; a2.z += v2.z; a2.w += v2.w;
    }
    float s = g_invcnt[w];
    float vals[12] = {a0.x*s, a0.y*s, a0.z*s, a0.w*s,
                      a1.x*s, a1.y*s, a1.z*s, a1.w*s,
                      a2.x*s, a2.y*s, a2.z*s, a2.w*s};
    size_t base = (size_t)w * H + lane * 4;
#pragma unroll
    for (int g = 0; g < 3; g++) {
#pragma unroll
        for (int j = 0; j < 4; j++) {
            float v = vals[g * 4 + j];
            bf16 hb = __float2bfloat16(v);
            ohi[base + g * 128 + j] = hb;
            olo[base + g * 128 + j] = __float2bfloat16(v - __bfloat162float(hb));
        }
    }
}

// ---------------- mma helpers ----------------
__device__ __forceinline__ void ldsm_x4(uint32_t* r, const void* p) {
    uint32_t a = (uint32_t)__cvta_generic_to_shared(p);
    asm volatile("ldmatrix.sync.aligned.m8n8.x4.shared.b16 {%0,%1,%2,%3}, [%4];"
                 : "=r"(r[0]), "=r"(r[1]), "=r"(r[2]), "=r"(r[3]) : "r"(a));
}
__device__ __forceinline__ void ldsm_x2t(uint32_t* r, const void* p) {
    uint32_t a = (uint32_t)__cvta_generic_to_shared(p);
    asm volatile("ldmatrix.sync.aligned.m8n8.x2.trans.shared.b16 {%0,%1}, [%2];"
                 : "=r"(r[0]), "=r"(r[1]) : "r"(a));
}
__device__ __forceinline__ void mma16816(float* d, const uint32_t* a, const uint32_t* b) {
    asm volatile("mma.sync.aligned.m16n8k16.row.col.f32.bf16.bf16.f32 "
                 "{%0,%1,%2,%3}, {%4,%5,%6,%7}, {%8,%9}, {%0,%1,%2,%3};"
                 : "+f"(d[0]), "+f"(d[1]), "+f"(d[2]), "+f"(d[3])
                 : "r"(a[0]), "r"(a[1]), "r"(a[2]), "r"(a[3]), "r"(b[0]), "r"(b[1]));
}
__device__ __forceinline__ void cpasync16(void* dst, const void* src, bool pred) {
    uint32_t d = (uint32_t)__cvta_generic_to_shared(dst);
    int sz = pred ? 16 : 0;
    asm volatile("cp.async.cg.shared.global [%0], [%1], 16, %2;"
                 :: "r"(d), "l"(src), "r"(sz) : "memory");
}
#define CP_COMMIT() asm volatile("cp.async.commit_group;" ::: "memory")
#define CP_WAIT1()  asm volatile("cp.async.wait_group 1;" ::: "memory")
#define CP_WAIT0()  asm volatile("cp.async.wait_group 0;" ::: "memory")

// ---------------- bf16x3 tensor-core GEMM, cp.async double-buffered ----------------
// C[M,Nc] (+)= A1[M,K1]@B1[K1,Nc] (+ A2[M,K2]@B2[K2,Nc]); bf16x3 splits.
// flags: 1=+bias, 2=acc C, 4=relu. ohi/olo optional split outputs.
// Per stage: Ah(128x40) Al(128x40) Bh(32x136) Bl(32x136) bf16.
static const int A_PITCH = 40;
static const int B_PITCH = 136;
static const int A_ELEMS = 128 * A_PITCH;   // 5120
static const int B_ELEMS = 32 * B_PITCH;    // 4352
static const int STAGE_ELEMS = 2 * A_ELEMS + 2 * B_ELEMS;   // 18944 bf16 = 37888 B
static const int SMEM_DYN = 2 * STAGE_ELEMS * 2;            // 75776 B

struct ChunkSrc { const bf16 *ah, *al, *bh, *bl; int K, kk; };

__global__ void __launch_bounds__(256) gemm_mma_kernel(
    const bf16* __restrict__ a1h, const bf16* __restrict__ a1l,
    const bf16* __restrict__ b1h, const bf16* __restrict__ b1l, int K1,
    const bf16* __restrict__ a2h, const bf16* __restrict__ a2l,
    const bf16* __restrict__ b2h, const bf16* __restrict__ b2l, int K2,
    const float* __restrict__ bias, float* __restrict__ C,
    bf16* __restrict__ ohi, bf16* __restrict__ olo,
    int M, int Nc, int flags)
{
    extern __shared__ bf16 sm[];

    const int tid  = threadIdx.x;
    const int lane = tid & 31;
    const int wid  = tid >> 5;
    const int wm   = (wid >> 2) * 64;
    const int wn   = (wid & 3) * 32;
    const int m0   = blockIdx.y * 128;
    const int n0   = blockIdx.x * 128;

    const int nch1 = K1 >> 5;
    const int nch2 = (a2h != nullptr) ? (K2 >> 5) : 0;
    const int NCH  = nch1 + nch2;

    float acc[4][4][4];
#pragma unroll
    for (int i = 0; i < 4; i++)
#pragma unroll
        for (int j = 0; j < 4; j++)
#pragma unroll
            for (int k = 0; k < 4; k++) acc[i][j][k] = 0.f;

    // ---- stage loader: issues 16 cp.async per thread (A 4 + A 4 + B 4 + B 4 is 2+2+2+2=8/thread) ----
    auto load_stage = [&](int buf, int c) {
        const bf16 *ah, *al, *bh, *bl; int K, kk;
        if (c < nch1) { ah = a1h; al = a1l; bh = b1h; bl = b1l; K = K1; kk = c * 32; }
        else          { ah = a2h; al = a2l; bh = b2h; bl = b2l; K = K2; kk = (c - nch1) * 32; }
        bf16* AhS = sm + buf * STAGE_ELEMS;
        bf16* AlS = AhS + A_ELEMS;
        bf16* BhS = AlS + A_ELEMS;
        bf16* BlS = BhS + B_ELEMS;
        // A: 128 rows x 32 cols, 512 16B-chunks per split; 2 per thread
#pragma unroll
        for (int t = 0; t < 2; t++) {
            int idx = tid + t * 256;          // 0..511
            int row = idx >> 2, cg = idx & 3;
            int gr = m0 + row;
            bool ok = gr < M;
            size_t so = (size_t)gr * K + kk + cg * 8;
            int doff = row * A_PITCH + cg * 8;
            cpasync16(AhS + doff, ah + (ok ? so : 0), ok);
            cpasync16(AlS + doff, al + (ok ? so : 0), ok);
        }
        // B: 32 rows x 128 cols, 512 chunks per split; 2 per thread
#pragma unroll
        for (int t = 0; t < 2; t++) {
            int idx = tid + t * 256;
            int row = idx >> 4, cg = idx & 15;
            int gc = n0 + cg * 8;
            bool ok = gc < Nc;
            size_t so = (size_t)(kk + row) * Nc + (ok ? gc : 0);
            int doff = row * B_PITCH + cg * 8;
            cpasync16(BhS + doff, bh + so, ok);
            cpasync16(BlS + doff, bl + so, ok);
        }
    };

    auto compute_stage = [&](int buf) {
        const bf16* AhS = sm + buf * STAGE_ELEMS;
        const bf16* AlS = AhS + A_ELEMS;
        const bf16* BhS = AlS + A_ELEMS;
        const bf16* BlS = BhS + B_ELEMS;
#pragma unroll
        for (int ks = 0; ks < 2; ks++) {
#pragma unroll
            for (int s = 0; s < 3; s++) {
                const bf16* As = (s == 2) ? AlS : AhS;
                const bf16* Bs = (s == 1) ? BlS : BhS;
                uint32_t af[4][4], bfr[4][2];
#pragma unroll
                for (int mi = 0; mi < 4; mi++)
                    ldsm_x4(af[mi], As + (wm + mi * 16 + (lane & 15)) * A_PITCH
                                       + ks * 16 + (lane >> 4) * 8);
#pragma unroll
                for (int ni = 0; ni < 4; ni++)
                    ldsm_x2t(bfr[ni], Bs + (ks * 16 + (lane & 15)) * B_PITCH + wn + ni * 8);
#pragma unroll
                for (int mi = 0; mi < 4; mi++)
#pragma unroll
                    for (int ni = 0; ni < 4; ni++)
                        mma16816(acc[mi][ni], af[mi], bfr[ni]);
            }
        }
    };

    // ---- software pipeline: prefetch c+1 while computing c ----
    load_stage(0, 0);
    CP_COMMIT();
    for (int c = 0; c < NCH; c++) {
        if (c + 1 < NCH) load_stage((c + 1) & 1, c + 1);
        CP_COMMIT();
        CP_WAIT1();
        __syncthreads();
        compute_stage(c & 1);
        __syncthreads();
    }
    CP_WAIT0();

    // ---- epilogue ----
#pragma unroll
    for (int mi = 0; mi < 4; mi++) {
#pragma unroll
        for (int ni = 0; ni < 4; ni++) {
            int rbase = m0 + wm + mi * 16 + (lane >> 2);
            int cbase = n0 + wn + ni * 8 + (lane & 3) * 2;
#pragma unroll
            for (int half = 0; half < 2; half++) {
                int r = rbase + half * 8;
                if (r < M) {
#pragma unroll
                    for (int j = 0; j < 2; j++) {
                        int c = cbase + j;
                        if (c < Nc) {
                            float v = acc[mi][ni][half * 2 + j];
                            if (flags & 1) v += bias[c];
                            if (flags & 2) v += C[(size_t)r * Nc + c];
                            if (flags & 4) v = fmaxf(v, 0.f);
                            C[(size_t)r * Nc + c] = v;
                            if (ohi) {
                                bf16 hv = __float2bfloat16(v);
                                ohi[(size_t)r * Nc + c] = hv;
                                olo[(size_t)r * Nc + c] =
                                    __float2bfloat16(v - __bfloat162float(hv));
                            }
                        }
                    }
                }
            }
        }
    }
}

// ---------------- batchnorm ----------------
__global__ void bn_stats_kernel(const float* __restrict__ h) {
    int c = threadIdx.x;
    float s = 0.f, s2 = 0.f;
    for (int r = blockIdx.x; r < N_NODES; r += gridDim.x) {
        float v = h[(size_t)r * H + c];
        s += v; s2 += v * v;
    }
    atomicAdd(&g_stats[c], s);
    atomicAdd(&g_stats[H + c], s2);
}

__global__ void bn_final_kernel(const float* __restrict__ g, const float* __restrict__ b) {
    int c = threadIdx.x;
    if (c < H) {
        float inv = 1.0f / (float)N_NODES;
        float mu  = g_stats[c] * inv;
        float var = g_stats[H + c] * inv - mu * mu;
        float rs  = rsqrtf(var + EPSV);
        float a   = g[c] * rs;
        g_bna[c] = a;
        g_bnc[c] = b[c] - mu * a;
    }
}

__global__ void bn_apply_relu_kernel(float* __restrict__ h,
                                     bf16* __restrict__ ohi, bf16* __restrict__ olo) {
    int i = blockIdx.x * blockDim.x + threadIdx.x;
    const int total = N_NODES * H / 4;
    if (i >= total) return;
    int c4 = i % (H / 4);
    float4 v = ((float4*)h)[i];
    float4 a = ((const float4*)g_bna)[c4];
    float4 c = ((const float4*)g_bnc)[c4];
    v.x = fmaxf(fmaf(v.x, a.x, c.x), 0.f);
    v.y = fmaxf(fmaf(v.y, a.y, c.y), 0.f);
    v.z = fmaxf(fmaf(v.z, a.z, c.z), 0.f);
    v.w = fmaxf(fmaf(v.w, a.w, c.w), 0.f);
    ((float4*)h)[i] = v;
    if (ohi) {
        size_t base = (size_t)i * 4;
        float vv[4] = {v.x, v.y, v.z, v.w};
        bf16 hb[4], lb[4];
#pragma unroll
        for (int j = 0; j < 4; j++) {
            hb[j] = __float2bfloat16(vv[j]);
            lb[j] = __float2bfloat16(vv[j] - __bfloat162float(hb[j]));
        }
        ((__nv_bfloat162*)(ohi + base))[0] = __halves2bfloat162(hb[0], hb[1]);
        ((__nv_bfloat162*)(ohi + base))[1] = __halves2bfloat162(hb[2], hb[3]);
        ((__nv_bfloat162*)(olo + base))[0] = __halves2bfloat162(lb[0], lb[1]);
        ((__nv_bfloat162*)(olo + base))[1] = __halves2bfloat162(lb[2], lb[3]);
    }
}

// ---------------- final tiny GEMM ----------------
__global__ void head3_kernel(const float* __restrict__ t2, const float* __restrict__ W3,
                             const float* __restrict__ b3, float* __restrict__ out) {
    __shared__ float w[96 * 2];
    __shared__ float bb[2];
    if (threadIdx.x < 192) w[threadIdx.x] = W3[threadIdx.x];
    if (threadIdx.x < 2)   bb[threadIdx.x] = b3[threadIdx.x];
    __syncthreads();
    int r = blockIdx.x * blockDim.x + threadIdx.x;
    if (r >= N_NODES) return;
    float a0 = bb[0], a1 = bb[1];
    const float* row = t2 + (size_t)r * 96;
#pragma unroll 8
    for (int k = 0; k < 96; k++) {
        float v = row[k];
        a0 = fmaf(v, w[k * 2],     a0);
        a1 = fmaf(v, w[k * 2 + 1], a1);
    }
    out[r * 2]     = a0;
    out[r * 2 + 1] = a1;
}

// ---------------- host orchestration ----------------
static void run_split(const float* src, bf16* hi, bf16* lo, size_t n) {
    split_kernel<<<(int)((n + 255) / 256), 256>>>(src, hi, lo, (int)n);
}

static void run_gemm(const bf16* a1h, const bf16* a1l, const bf16* b1h, const bf16* b1l, int K1,
                     const bf16* a2h, const bf16* a2l, const bf16* b2h, const bf16* b2l, int K2,
                     const float* bias, float* C, bf16* ohi, bf16* olo,
                     int M, int Nc, int flags) {
    static int attr_set = 0;
    if (!attr_set) {
        cudaFuncSetAttribute(gemm_mma_kernel,
                             cudaFuncAttributeMaxDynamicSharedMemorySize, SMEM_DYN);
        attr_set = 1;
    }
    dim3 grid((Nc + 127) / 128, (M + 127) / 128);
    gemm_mma_kernel<<<grid, 256, SMEM_DYN>>>(a1h, a1l, b1h, b1l, K1,
                                             a2h, a2l, b2h, b2l, K2,
                                             bias, C, ohi, olo, M, Nc, flags);
}

extern "C" void kernel_launch(void* const* d_in, const int* in_sizes, int n_in,
                              void* d_out, int out_size) {
    const float* x     = (const float*)d_in[0];
    const int*   ei    = (const int*)  d_in[1];
    const float* W_in  = (const float*)d_in[2];
    const float* b_in  = (const float*)d_in[3];
    const float* bn0_g = (const float*)d_in[4];
    const float* bn0_b = (const float*)d_in[5];
    const float* Wl    = (const float*)d_in[6];
    const float* bl    = (const float*)d_in[7];
    const float* Wr    = (const float*)d_in[8];
    const float* bn_g  = (const float*)d_in[9];
    const float* bn_b  = (const float*)d_in[10];
    const float* Wskip = (const float*)d_in[11];
    const float* bskip = (const float*)d_in[12];
    const float* W1    = (const float*)d_in[13];
    const float* b1    = (const float*)d_in[14];
    const float* W2    = (const float*)d_in[15];
    const float* b2    = (const float*)d_in[16];
    const float* W3    = (const float*)d_in[17];
    const float* b3    = (const float*)d_in[18];

    float* logits_out = (float*)d_out;
    float* emb_out    = logits_out + (size_t)N_NODES * NCLS;

    float *hf, *tf, *t1f, *stats;
    int *deg, *colptr, *cursor;
    bf16* bfb;
    cudaGetSymbolAddress((void**)&hf,     g_h);
    cudaGetSymbolAddress((void**)&tf,     g_tmp);
    cudaGetSymbolAddress((void**)&t1f,    g_t1f);
    cudaGetSymbolAddress((void**)&stats,  g_stats);
    cudaGetSymbolAddress((void**)&deg,    g_deg);
    cudaGetSymbolAddress((void**)&colptr, g_colptr);
    cudaGetSymbolAddress((void**)&cursor, g_cursor);
    cudaGetSymbolAddress((void**)&bfb,    g_bf);

    bf16 *hsH = bfb + OFF_HSA_H, *hsL = bfb + OFF_HSA_L;
    bf16 *tsH = bfb + OFF_HSB_H, *tsL = bfb + OFF_HSB_L;
    bf16 *agH = bfb + OFF_AGG_H, *agL = bfb + OFF_AGG_L;
    bf16 *xH  = bfb + OFF_X_H,   *xL  = bfb + OFF_X_L;
    bf16 *t1H = bfb + OFF_T1_H,  *t1L = bfb + OFF_T1_L;
    bf16 *WinH = bfb + OFF_WIN_H, *WinL = bfb + OFF_WIN_L;
    bf16 *WlH  = bfb + OFF_WL_H,  *WlL  = bfb + OFF_WL_L;
    bf16 *WrH  = bfb + OFF_WR_H,  *WrL  = bfb + OFF_WR_L;
    bf16 *WskH = bfb + OFF_WSK_H, *WskL = bfb + OFF_WSK_L;
    bf16 *W1H  = bfb + OFF_W1_H,  *W1L  = bfb + OFF_W1_L;
    bf16 *W2H  = bfb + OFF_W2_H,  *W2L  = bfb + OFF_W2_L;

    const int* e_row = ei;
    const int* e_col = ei + N_EDGES;

    // ---- CSR build ----
    cudaMemsetAsync(deg, 0, N_NODES * sizeof(int));
    hist_kernel<<<(N_EDGES + 255) / 256, 256>>>(e_col);
    scan_kernel<<<1, 1024>>>();
    cudaMemcpyAsync(cursor, colptr, N_NODES * sizeof(int), cudaMemcpyDeviceToDevice);
    fill_kernel<<<(N_EDGES + 255) / 256, 256>>>(e_row, e_col);
    invcnt_kernel<<<(N_NODES + 255) / 256, 256>>>();

    // ---- split weights + x into bf16 hi/lo ----
    run_split(W_in,  WinH, WinL, SZ_WIN);
    run_split(Wl,    WlH,  WlL,  SZ_WL);
    run_split(Wr,    WrH,  WrL,  SZ_WL);
    run_split(Wskip, WskH, WskL, SZ_WSK);
    run_split(W1,    W1H,  W1L,  SZ_W1);
    run_split(W2,    W2H,  W2L,  SZ_W2);
    run_split(x,     xH,   xL,   (size_t)N_NODES * DIN);

    // ---- input layer: h = relu(bn0(x @ W_in + b_in)) ----
    run_gemm(xH, xL, WinH, WinL, DIN,
             nullptr, nullptr, nullptr, nullptr, 0,
             b_in, hf, nullptr, nullptr, N_NODES, H, /*bias*/1);
    cudaMemsetAsync(stats, 0, 2 * H * sizeof(float));
    bn_stats_kernel<<<256, H>>>(hf);
    bn_final_kernel<<<1, H>>>(bn0_g, bn0_b);
    {
        int total4 = N_NODES * H / 4;
        bn_apply_relu_kernel<<<(total4 + 255) / 256, 256>>>(hf, hsH, hsL);
    }

    // ---- SAGE layers ----
    int skip = 0;
    for (int i = 0; i < NLAYERS; i++) {
        bool is_skip = ((i & 1) == 1);
        agg_kernel<<<(N_NODES * 32 + 255) / 256, 256>>>(hf, agH, agL);
        // tmp = agg@Wl[i] + bl[i] + h@Wr[i]   (fused 2-pass GEMM)
        run_gemm(agH, agL, WlH + (size_t)i * H * H, WlL + (size_t)i * H * H, H,
                 hsH, hsL, WrH + (size_t)i * H * H, WrL + (size_t)i * H * H, H,
                 bl + (size_t)i * H, tf, nullptr, nullptr, N_NODES, H, /*bias*/1);
        cudaMemsetAsync(stats, 0, 2 * H * sizeof(float));
        bn_stats_kernel<<<256, H>>>(tf);
        bn_final_kernel<<<1, H>>>(bn_g + (size_t)i * H, bn_b + (size_t)i * H);
        {
            int total4 = N_NODES * H / 4;
            bn_apply_relu_kernel<<<(total4 + 255) / 256, 256>>>(
                tf, is_skip ? nullptr : tsH, is_skip ? nullptr : tsL);
        }
        if (is_skip) {
            run_gemm(hsH, hsL, WskH + (size_t)skip * H * H, WskL + (size_t)skip * H * H, H,
                     nullptr, nullptr, nullptr, nullptr, 0,
                     bskip + (size_t)skip * H, tf, tsH, tsL, N_NODES, H, /*bias|acc*/3);
            skip++;
        }
        float* ft = hf; hf = tf; tf = ft;
        bf16* bt;
        bt = hsH; hsH = tsH; tsH = bt;
        bt = hsL; hsL = tsL; tsL = bt;
    }

    // ---- outputs: embeddings + MLP head ----
    cudaMemcpyAsync(emb_out, hf, (size_t)N_NODES * H * sizeof(float),
                    cudaMemcpyDeviceToDevice);
    run_gemm(hsH, hsL, W1H, W1L, H,
             nullptr, nullptr, nullptr, nullptr, 0,
             b1, t1f, t1H, t1L, N_NODES, H / 2, /*bias|relu*/5);
    run_gemm(t1H, t1L, W2H, W2L, H / 2,
             nullptr, nullptr, nullptr, nullptr, 0,
             b2, tf, nullptr, nullptr, N_NODES, H / 4, /*bias|relu*/5);
    head3_kernel<<<(N_NODES + 255) / 256, 256>>>(tf, W3, b3, logits_out);
}

// round 11
// speedup vs baseline: 2.8341x; 1.0848x over previous
#include <cuda_runtime.h>
#include <cuda_bf16.h>
#include <math.h>
#include <stdint.h>

#define N_NODES 50000
#define N_EDGES 800000
#define DIN     256
#define H       384
#define NLAYERS 6
#define NCLS    2
#define EPSV    1e-5f

typedef __nv_bfloat16 bf16;

// ---------------- fp32 scratch ----------------
__device__ float g_h   [(size_t)N_NODES * H];
__device__ float g_tmp [(size_t)N_NODES * H];
__device__ float g_t1f [(size_t)N_NODES * H];
__device__ float g_stats[2 * H];
__device__ float g_bna [H];
__device__ float g_bnc [H];
__device__ float g_invcnt[N_NODES];
__device__ int   g_deg   [N_NODES];
__device__ int   g_colptr[N_NODES + 1];
__device__ int   g_cursor[N_NODES];
__device__ int   g_src   [N_EDGES];

// ---------------- bf16 split scratch ----------------
#define NH ((size_t)N_NODES * H)
static const size_t OFF_HSA_H = 0;
static const size_t OFF_HSA_L = 1 * NH;
static const size_t OFF_HSB_H = 2 * NH;
static const size_t OFF_HSB_L = 3 * NH;
static const size_t OFF_AGG_H = 4 * NH;
static const size_t OFF_AGG_L = 5 * NH;
static const size_t OFF_X_H   = 6 * NH;
static const size_t OFF_X_L   = 7 * NH;
static const size_t OFF_T1_H  = 8 * NH;
static const size_t OFF_T1_L  = 9 * NH;
static const size_t SZ_WIN = (size_t)DIN * H;
static const size_t SZ_WL  = (size_t)NLAYERS * H * H;
static const size_t SZ_WSK = (size_t)(NLAYERS / 2) * H * H;
static const size_t SZ_W1  = (size_t)H * (H / 2);
static const size_t SZ_W2  = (size_t)(H / 2) * (H / 4);
static const size_t OFF_WIN_H = 10 * NH;
static const size_t OFF_WIN_L = OFF_WIN_H + SZ_WIN;
static const size_t OFF_WL_H  = OFF_WIN_L + SZ_WIN;
static const size_t OFF_WL_L  = OFF_WL_H + SZ_WL;
static const size_t OFF_WR_H  = OFF_WL_L + SZ_WL;
static const size_t OFF_WR_L  = OFF_WR_H + SZ_WL;
static const size_t OFF_WSK_H = OFF_WR_L + SZ_WL;
static const size_t OFF_WSK_L = OFF_WSK_H + SZ_WSK;
static const size_t OFF_W1_H  = OFF_WSK_L + SZ_WSK;
static const size_t OFF_W1_L  = OFF_W1_H + SZ_W1;
static const size_t OFF_W2_H  = OFF_W1_L + SZ_W1;
static const size_t OFF_W2_L  = OFF_W2_H + SZ_W2;
static const size_t BF_TOTAL  = OFF_W2_L + SZ_W2;

__device__ bf16 g_bf[BF_TOTAL];

// ---------------- CSR build ----------------
__global__ void hist_kernel(const int* __restrict__ col) {
    int i = blockIdx.x * blockDim.x + threadIdx.x;
    if (i < N_EDGES) atomicAdd(&g_deg[col[i]], 1);
}

__global__ void scan_kernel() {
    __shared__ int buf[1024];
    int tid = threadIdx.x;
    int offset = 0;
    for (int base = 0; base < N_NODES; base += 1024) {
        int idx = base + tid;
        int v = (idx < N_NODES) ? g_deg[idx] : 0;
        buf[tid] = v;
        __syncthreads();
        for (int s = 1; s < 1024; s <<= 1) {
            int t = (tid >= s) ? buf[tid - s] : 0;
            __syncthreads();
            buf[tid] += t;
            __syncthreads();
        }
        if (idx < N_NODES) g_colptr[idx] = offset + buf[tid] - v;
        int tot = buf[1023];
        __syncthreads();
        offset += tot;
    }
    if (tid == 0) g_colptr[N_NODES] = offset;
}

__global__ void fill_kernel(const int* __restrict__ row, const int* __restrict__ col) {
    int i = blockIdx.x * blockDim.x + threadIdx.x;
    if (i < N_EDGES) {
        int p = atomicAdd(&g_cursor[col[i]], 1);
        g_src[p] = row[i];
    }
}

__global__ void invcnt_kernel() {
    int i = blockIdx.x * blockDim.x + threadIdx.x;
    if (i < N_NODES) g_invcnt[i] = 1.0f / fmaxf((float)g_deg[i], 1.0f);
}

// ---------------- splits ----------------
__global__ void split_kernel(const float* __restrict__ src,
                             bf16* __restrict__ hi, bf16* __restrict__ lo, int n) {
    int i = blockIdx.x * blockDim.x + threadIdx.x;
    if (i < n) {
        float v = src[i];
        bf16 h = __float2bfloat16(v);
        hi[i] = h;
        lo[i] = __float2bfloat16(v - __bfloat162float(h));
    }
}

// ---------------- mean aggregation ----------------
__global__ void agg_kernel(const float* __restrict__ h,
                           bf16* __restrict__ ohi, bf16* __restrict__ olo) {
    int w    = (blockIdx.x * blockDim.x + threadIdx.x) >> 5;
    int lane = threadIdx.x & 31;
    if (w >= N_NODES) return;
    int beg = g_colptr[w], end = g_colptr[w + 1];
    float4 a0 = make_float4(0.f, 0.f, 0.f, 0.f);
    float4 a1 = a0, a2 = a0;
    for (int e = beg; e < end; e++) {
        const float4* hp = (const float4*)(h + (size_t)g_src[e] * H);
        float4 v0 = hp[lane];
        float4 v1 = hp[lane + 32];
        float4 v2 = hp[lane + 64];
        a0.x += v0.x; a0.y += v0.y; a0.z += v0.z; a0.w += v0.w;
        a1.x += v1.x; a1.y += v1.y; a1.z += v1.z; a1.w += v1.w;
        a2.x += v2.x; a2.y += v2.y; a2.z += v2.z; a2.w += v2.w;
    }
    float s = g_invcnt[w];
    float vals[12] = {a0.x*s, a0.y*s, a0.z*s, a0.w*s,
                      a1.x*s, a1.y*s, a1.z*s, a1.w*s,
                      a2.x*s, a2.y*s, a2.z*s, a2.w*s};
    size_t base = (size_t)w * H + lane * 4;
#pragma unroll
    for (int g = 0; g < 3; g++) {
#pragma unroll
        for (int j = 0; j < 4; j++) {
            float v = vals[g * 4 + j];
            bf16 hb = __float2bfloat16(v);
            ohi[base + g * 128 + j] = hb;
            olo[base + g * 128 + j] = __float2bfloat16(v - __bfloat162float(hb));
        }
    }
}

// ---------------- mma helpers ----------------
__device__ __forceinline__ void ldsm_x4(uint32_t* r, const void* p) {
    uint32_t a = (uint32_t)__cvta_generic_to_shared(p);
    asm volatile("ldmatrix.sync.aligned.m8n8.x4.shared.b16 {%0,%1,%2,%3}, [%4];"
                 : "=r"(r[0]), "=r"(r[1]), "=r"(r[2]), "=r"(r[3]) : "r"(a));
}
__device__ __forceinline__ void ldsm_x2t(uint32_t* r, const void* p) {
    uint32_t a = (uint32_t)__cvta_generic_to_shared(p);
    asm volatile("ldmatrix.sync.aligned.m8n8.x2.trans.shared.b16 {%0,%1}, [%2];"
                 : "=r"(r[0]), "=r"(r[1]) : "r"(a));
}
__device__ __forceinline__ void mma16816(float* d, const uint32_t* a, const uint32_t* b) {
    asm volatile("mma.sync.aligned.m16n8k16.row.col.f32.bf16.bf16.f32 "
                 "{%0,%1,%2,%3}, {%4,%5,%6,%7}, {%8,%9}, {%0,%1,%2,%3};"
                 : "+f"(d[0]), "+f"(d[1]), "+f"(d[2]), "+f"(d[3])
                 : "r"(a[0]), "r"(a[1]), "r"(a[2]), "r"(a[3]), "r"(b[0]), "r"(b[1]));
}
__device__ __forceinline__ void cpasync16(void* dst, const void* src, bool pred) {
    uint32_t d = (uint32_t)__cvta_generic_to_shared(dst);
    int sz = pred ? 16 : 0;
    asm volatile("cp.async.cg.shared.global [%0], [%1], 16, %2;"
                 :: "r"(d), "l"(src), "r"(sz) : "memory");
}
#define CP_COMMIT() asm volatile("cp.async.commit_group;" ::: "memory")
#define CP_WAIT1()  asm volatile("cp.async.wait_group 1;" ::: "memory")
#define CP_WAIT0()  asm volatile("cp.async.wait_group 0;" ::: "memory")

// ---------------- bf16x3 tensor-core GEMM, cp.async double-buffered ----------------
// flags: 1=+bias, 2=acc C, 4=relu, 8=fused BN col-stats, 16=skip-BN (v = relu(bn(Cin)) + acc + bias)
static const int A_PITCH = 40;
static const int B_PITCH = 136;
static const int A_ELEMS = 128 * A_PITCH;
static const int B_ELEMS = 32 * B_PITCH;
static const int STAGE_ELEMS = 2 * A_ELEMS + 2 * B_ELEMS;
static const int SMEM_DYN = 2 * STAGE_ELEMS * 2;

__global__ void __launch_bounds__(256) gemm_mma_kernel(
    const bf16* __restrict__ a1h, const bf16* __restrict__ a1l,
    const bf16* __restrict__ b1h, const bf16* __restrict__ b1l, int K1,
    const bf16* __restrict__ a2h, const bf16* __restrict__ a2l,
    const bf16* __restrict__ b2h, const bf16* __restrict__ b2l, int K2,
    const float* __restrict__ bias,
    const float* __restrict__ Cin, float* __restrict__ Cout,
    bf16* __restrict__ ohi, bf16* __restrict__ olo,
    int M, int Nc, int flags)
{
    extern __shared__ bf16 sm[];

    const int tid  = threadIdx.x;
    const int lane = tid & 31;
    const int wid  = tid >> 5;
    const int wm   = (wid >> 2) * 64;
    const int wn   = (wid & 3) * 32;
    const int m0   = blockIdx.y * 128;
    const int n0   = blockIdx.x * 128;

    const int nch1 = K1 >> 5;
    const int nch2 = (a2h != nullptr) ? (K2 >> 5) : 0;
    const int NCH  = nch1 + nch2;

    float acc[4][4][4];
#pragma unroll
    for (int i = 0; i < 4; i++)
#pragma unroll
        for (int j = 0; j < 4; j++)
#pragma unroll
            for (int k = 0; k < 4; k++) acc[i][j][k] = 0.f;

    auto load_stage = [&](int buf, int c) {
        const bf16 *ah, *al, *bh, *bl; int K, kk;
        if (c < nch1) { ah = a1h; al = a1l; bh = b1h; bl = b1l; K = K1; kk = c * 32; }
        else          { ah = a2h; al = a2l; bh = b2h; bl = b2l; K = K2; kk = (c - nch1) * 32; }
        bf16* AhS = sm + buf * STAGE_ELEMS;
        bf16* AlS = AhS + A_ELEMS;
        bf16* BhS = AlS + A_ELEMS;
        bf16* BlS = BhS + B_ELEMS;
#pragma unroll
        for (int t = 0; t < 2; t++) {
            int idx = tid + t * 256;
            int row = idx >> 2, cg = idx & 3;
            int gr = m0 + row;
            bool ok = gr < M;
            size_t so = (size_t)gr * K + kk + cg * 8;
            int doff = row * A_PITCH + cg * 8;
            cpasync16(AhS + doff, ah + (ok ? so : 0), ok);
            cpasync16(AlS + doff, al + (ok ? so : 0), ok);
        }
#pragma unroll
        for (int t = 0; t < 2; t++) {
            int idx = tid + t * 256;
            int row = idx >> 4, cg = idx & 15;
            int gc = n0 + cg * 8;
            bool ok = gc < Nc;
            size_t so = (size_t)(kk + row) * Nc + (ok ? gc : 0);
            int doff = row * B_PITCH + cg * 8;
            cpasync16(BhS + doff, bh + so, ok);
            cpasync16(BlS + doff, bl + so, ok);
        }
    };

    // fragment-reuse compute: per K16 step load Bh,Bl,Ah once; mma(Ah,Bh), mma(Ah,Bl);
    // reload A regs with Al; mma(Al,Bh).  8 ldsm_x4 + 8 ldsm_x2t per step (was 12+12).
    auto compute_stage = [&](int buf) {
        const bf16* AhS = sm + buf * STAGE_ELEMS;
        const bf16* AlS = AhS + A_ELEMS;
        const bf16* BhS = AlS + A_ELEMS;
        const bf16* BlS = BhS + B_ELEMS;
        (void)BlS;
#pragma unroll
        for (int ks = 0; ks < 2; ks++) {
            uint32_t bfh[4][2], bfl[4][2], af[4][4];
#pragma unroll
            for (int ni = 0; ni < 4; ni++) {
                const bf16* bb = BhS + (ks * 16 + (lane & 15)) * B_PITCH + wn + ni * 8;
                ldsm_x2t(bfh[ni], bb);
                ldsm_x2t(bfl[ni], bb + B_ELEMS);   // BlS at fixed offset from BhS
            }
#pragma unroll
            for (int mi = 0; mi < 4; mi++)
                ldsm_x4(af[mi], AhS + (wm + mi * 16 + (lane & 15)) * A_PITCH
                                   + ks * 16 + (lane >> 4) * 8);
#pragma unroll
            for (int mi = 0; mi < 4; mi++)
#pragma unroll
                for (int ni = 0; ni < 4; ni++)
                    mma16816(acc[mi][ni], af[mi], bfh[ni]);
#pragma unroll
            for (int mi = 0; mi < 4; mi++)
#pragma unroll
                for (int ni = 0; ni < 4; ni++)
                    mma16816(acc[mi][ni], af[mi], bfl[ni]);
#pragma unroll
            for (int mi = 0; mi < 4; mi++)
                ldsm_x4(af[mi], AlS + (wm + mi * 16 + (lane & 15)) * A_PITCH
                                   + ks * 16 + (lane >> 4) * 8);
#pragma unroll
            for (int mi = 0; mi < 4; mi++)
#pragma unroll
                for (int ni = 0; ni < 4; ni++)
                    mma16816(acc[mi][ni], af[mi], bfh[ni]);
        }
    };

    load_stage(0, 0);
    CP_COMMIT();
    for (int c = 0; c < NCH; c++) {
        if (c + 1 < NCH) load_stage((c + 1) & 1, c + 1);
        CP_COMMIT();
        CP_WAIT1();
        __syncthreads();
        compute_stage(c & 1);
        __syncthreads();
    }
    CP_WAIT0();

    // ---- epilogue (smem now reusable as stats buffer) ----
    float* scol = (float*)sm;
    const bool do_stats = (flags & 8) != 0;
    if (do_stats) {
        if (tid < 256) scol[tid] = 0.f;
        __syncthreads();
    }

    float ls[4][2], ls2[4][2];
    if (do_stats) {
#pragma unroll
        for (int ni = 0; ni < 4; ni++) { ls[ni][0]=ls[ni][1]=ls2[ni][0]=ls2[ni][1]=0.f; }
    }

#pragma unroll
    for (int mi = 0; mi < 4; mi++) {
#pragma unroll
        for (int ni = 0; ni < 4; ni++) {
            int rbase = m0 + wm + mi * 16 + (lane >> 2);
            int cbase = n0 + wn + ni * 8 + (lane & 3) * 2;
#pragma unroll
            for (int half = 0; half < 2; half++) {
                int r = rbase + half * 8;
                if (r < M) {
#pragma unroll
                    for (int j = 0; j < 2; j++) {
                        int c = cbase + j;
                        if (c < Nc) {
                            float v = acc[mi][ni][half * 2 + j];
                            if (flags & 1) v += bias[c];
                            if (flags & 2) v += Cin[(size_t)r * Nc + c];
                            if (flags & 16) {
                                float old = Cin[(size_t)r * Nc + c];
                                v += fmaxf(fmaf(old, g_bna[c], g_bnc[c]), 0.f);
                            }
                            if (flags & 4) v = fmaxf(v, 0.f);
                            Cout[(size_t)r * Nc + c] = v;
                            if (do_stats) {
                                ls [ni][j] += v;
                                ls2[ni][j] = fmaf(v, v, ls2[ni][j]);
                            }
                            if (ohi) {
                                bf16 hv = __float2bfloat16(v);
                                ohi[(size_t)r * Nc + c] = hv;
                                olo[(size_t)r * Nc + c] =
                                    __float2bfloat16(v - __bfloat162float(hv));
                            }
                        }
                    }
                }
            }
        }
    }

    if (do_stats) {
#pragma unroll
        for (int ni = 0; ni < 4; ni++) {
#pragma unroll
            for (int j = 0; j < 2; j++) {
                int cloc = wn + ni * 8 + (lane & 3) * 2 + j;
                atomicAdd(&scol[cloc], ls[ni][j]);
                atomicAdd(&scol[128 + cloc], ls2[ni][j]);
            }
        }
        __syncthreads();
        if (tid < 128) {
            int c = n0 + tid;
            if (c < Nc) {
                atomicAdd(&g_stats[c],     scol[tid]);
                atomicAdd(&g_stats[H + c], scol[128 + tid]);
            }
        }
    }
}

// ---------------- batchnorm ----------------
__global__ void bn_final_kernel(const float* __restrict__ g, const float* __restrict__ b) {
    int c = threadIdx.x;
    if (c < H) {
        float inv = 1.0f / (float)N_NODES;
        float mu  = g_stats[c] * inv;
        float var = g_stats[H + c] * inv - mu * mu;
        float rs  = rsqrtf(var + EPSV);
        float a   = g[c] * rs;
        g_bna[c] = a;
        g_bnc[c] = b[c] - mu * a;
    }
}

__global__ void bn_apply_relu_kernel(float* __restrict__ h,
                                     bf16* __restrict__ ohi, bf16* __restrict__ olo) {
    int i = blockIdx.x * blockDim.x + threadIdx.x;
    const int total = N_NODES * H / 4;
    if (i >= total) return;
    int c4 = i % (H / 4);
    float4 v = ((float4*)h)[i];
    float4 a = ((const float4*)g_bna)[c4];
    float4 c = ((const float4*)g_bnc)[c4];
    v.x = fmaxf(fmaf(v.x, a.x, c.x), 0.f);
    v.y = fmaxf(fmaf(v.y, a.y, c.y), 0.f);
    v.z = fmaxf(fmaf(v.z, a.z, c.z), 0.f);
    v.w = fmaxf(fmaf(v.w, a.w, c.w), 0.f);
    ((float4*)h)[i] = v;
    if (ohi) {
        size_t base = (size_t)i * 4;
        float vv[4] = {v.x, v.y, v.z, v.w};
        bf16 hb[4], lb[4];
#pragma unroll
        for (int j = 0; j < 4; j++) {
            hb[j] = __float2bfloat16(vv[j]);
            lb[j] = __float2bfloat16(vv[j] - __bfloat162float(hb[j]));
        }
        ((__nv_bfloat162*)(ohi + base))[0] = __halves2bfloat162(hb[0], hb[1]);
        ((__nv_bfloat162*)(ohi + base))[1] = __halves2bfloat162(hb[2], hb[3]);
        ((__nv_bfloat162*)(olo + base))[0] = __halves2bfloat162(lb[0], lb[1]);
        ((__nv_bfloat162*)(olo + base))[1] = __halves2bfloat162(lb[2], lb[3]);
    }
}

// ---------------- final tiny GEMM ----------------
__global__ void head3_kernel(const float* __restrict__ t2, const float* __restrict__ W3,
                             const float* __restrict__ b3, float* __restrict__ out) {
    __shared__ float w[96 * 2];
    __shared__ float bb[2];
    if (threadIdx.x < 192) w[threadIdx.x] = W3[threadIdx.x];
    if (threadIdx.x < 2)   bb[threadIdx.x] = b3[threadIdx.x];
    __syncthreads();
    int r = blockIdx.x * blockDim.x + threadIdx.x;
    if (r >= N_NODES) return;
    float a0 = bb[0], a1 = bb[1];
    const float* row = t2 + (size_t)r * 96;
#pragma unroll 8
    for (int k = 0; k < 96; k++) {
        float v = row[k];
        a0 = fmaf(v, w[k * 2],     a0);
        a1 = fmaf(v, w[k * 2 + 1], a1);
    }
    out[r * 2]     = a0;
    out[r * 2 + 1] = a1;
}

// ---------------- host orchestration ----------------
static void run_split(const float* src, bf16* hi, bf16* lo, size_t n) {
    split_kernel<<<(int)((n + 255) / 256), 256>>>(src, hi, lo, (int)n);
}

static void run_gemm(const bf16* a1h, const bf16* a1l, const bf16* b1h, const bf16* b1l, int K1,
                     const bf16* a2h, const bf16* a2l, const bf16* b2h, const bf16* b2l, int K2,
                     const float* bias, const float* Cin, float* Cout, bf16* ohi, bf16* olo,
                     int M, int Nc, int flags) {
    static int attr_set = 0;
    if (!attr_set) {
        cudaFuncSetAttribute(gemm_mma_kernel,
                             cudaFuncAttributeMaxDynamicSharedMemorySize, SMEM_DYN);
        attr_set = 1;
    }
    dim3 grid((Nc + 127) / 128, (M + 127) / 128);
    gemm_mma_kernel<<<grid, 256, SMEM_DYN>>>(a1h, a1l, b1h, b1l, K1,
                                             a2h, a2l, b2h, b2l, K2,
                                             bias, Cin, Cout, ohi, olo, M, Nc, flags);
}

extern "C" void kernel_launch(void* const* d_in, const int* in_sizes, int n_in,
                              void* d_out, int out_size) {
    const float* x     = (const float*)d_in[0];
    const int*   ei    = (const int*)  d_in[1];
    const float* W_in  = (const float*)d_in[2];
    const float* b_in  = (const float*)d_in[3];
    const float* bn0_g = (const float*)d_in[4];
    const float* bn0_b = (const float*)d_in[5];
    const float* Wl    = (const float*)d_in[6];
    const float* bl    = (const float*)d_in[7];
    const float* Wr    = (const float*)d_in[8];
    const float* bn_g  = (const float*)d_in[9];
    const float* bn_b  = (const float*)d_in[10];
    const float* Wskip = (const float*)d_in[11];
    const float* bskip = (const float*)d_in[12];
    const float* W1    = (const float*)d_in[13];
    const float* b1    = (const float*)d_in[14];
    const float* W2    = (const float*)d_in[15];
    const float* b2    = (const float*)d_in[16];
    const float* W3    = (const float*)d_in[17];
    const float* b3    = (const float*)d_in[18];

    float* logits_out = (float*)d_out;
    float* emb_out    = logits_out + (size_t)N_NODES * NCLS;

    float *hf, *tf, *t1f, *stats;
    int *deg, *colptr, *cursor;
    bf16* bfb;
    cudaGetSymbolAddress((void**)&hf,     g_h);
    cudaGetSymbolAddress((void**)&tf,     g_tmp);
    cudaGetSymbolAddress((void**)&t1f,    g_t1f);
    cudaGetSymbolAddress((void**)&stats,  g_stats);
    cudaGetSymbolAddress((void**)&deg,    g_deg);
    cudaGetSymbolAddress((void**)&colptr, g_colptr);
    cudaGetSymbolAddress((void**)&cursor, g_cursor);
    cudaGetSymbolAddress((void**)&bfb,    g_bf);

    bf16 *hsH = bfb + OFF_HSA_H, *hsL = bfb + OFF_HSA_L;
    bf16 *tsH = bfb + OFF_HSB_H, *tsL = bfb + OFF_HSB_L;
    bf16 *agH = bfb + OFF_AGG_H, *agL = bfb + OFF_AGG_L;
    bf16 *xH  = bfb + OFF_X_H,   *xL  = bfb + OFF_X_L;
    bf16 *t1H = bfb + OFF_T1_H,  *t1L = bfb + OFF_T1_L;
    bf16 *WinH = bfb + OFF_WIN_H, *WinL = bfb + OFF_WIN_L;
    bf16 *WlH  = bfb + OFF_WL_H,  *WlL  = bfb + OFF_WL_L;
    bf16 *WrH  = bfb + OFF_WR_H,  *WrL  = bfb + OFF_WR_L;
    bf16 *WskH = bfb + OFF_WSK_H, *WskL = bfb + OFF_WSK_L;
    bf16 *W1H  = bfb + OFF_W1_H,  *W1L  = bfb + OFF_W1_L;
    bf16 *W2H  = bfb + OFF_W2_H,  *W2L  = bfb + OFF_W2_L;

    const int* e_row = ei;
    const int* e_col = ei + N_EDGES;

    // ---- CSR build ----
    cudaMemsetAsync(deg, 0, N_NODES * sizeof(int));
    hist_kernel<<<(N_EDGES + 255) / 256, 256>>>(e_col);
    scan_kernel<<<1, 1024>>>();
    cudaMemcpyAsync(cursor, colptr, N_NODES * sizeof(int), cudaMemcpyDeviceToDevice);
    fill_kernel<<<(N_EDGES + 255) / 256, 256>>>(e_row, e_col);
    invcnt_kernel<<<(N_NODES + 255) / 256, 256>>>();

    // ---- split weights + x ----
    run_split(W_in,  WinH, WinL, SZ_WIN);
    run_split(Wl,    WlH,  WlL,  SZ_WL);
    run_split(Wr,    WrH,  WrL,  SZ_WL);
    run_split(Wskip, WskH, WskL, SZ_WSK);
    run_split(W1,    W1H,  W1L,  SZ_W1);
    run_split(W2,    W2H,  W2L,  SZ_W2);
    run_split(x,     xH,   xL,   (size_t)N_NODES * DIN);

    // ---- input layer: h = relu(bn0(x @ W_in + b_in)); stats fused into epilogue ----
    cudaMemsetAsync(stats, 0, 2 * H * sizeof(float));
    run_gemm(xH, xL, WinH, WinL, DIN,
             nullptr, nullptr, nullptr, nullptr, 0,
             b_in, hf, hf, nullptr, nullptr, N_NODES, H, /*bias|stats*/9);
    bn_final_kernel<<<1, H>>>(bn0_g, bn0_b);
    {
        int total4 = N_NODES * H / 4;
        bn_apply_relu_kernel<<<(total4 + 255) / 256, 256>>>(hf, hsH, hsL);
    }

    // ---- SAGE layers ----
    int skip = 0;
    for (int i = 0; i < NLAYERS; i++) {
        bool is_skip = ((i & 1) == 1);
        agg_kernel<<<(N_NODES * 32 + 255) / 256, 256>>>(hf, agH, agL);
        // tmp = agg@Wl + bl + h@Wr (raw); col stats fused
        cudaMemsetAsync(stats, 0, 2 * H * sizeof(float));
        run_gemm(agH, agL, WlH + (size_t)i * H * H, WlL + (size_t)i * H * H, H,
                 hsH, hsL, WrH + (size_t)i * H * H, WrL + (size_t)i * H * H, H,
                 bl + (size_t)i * H, tf, tf, nullptr, nullptr, N_NODES, H, /*bias|stats*/9);
        bn_final_kernel<<<1, H>>>(bn_g + (size_t)i * H, bn_b + (size_t)i * H);
        if (is_skip) {
            // out = relu(bn(tf)) + identity@Wskip + bskip  (BN fused into skip epilogue)
            float* outp = (i == NLAYERS - 1) ? emb_out : tf;
            run_gemm(hsH, hsL, WskH + (size_t)skip * H * H, WskL + (size_t)skip * H * H, H,
                     nullptr, nullptr, nullptr, nullptr, 0,
                     bskip + (size_t)skip * H, tf, outp, tsH, tsL,
                     N_NODES, H, /*bias|skipBN*/17);
            skip++;
            if (i == NLAYERS - 1) {
                // final: fp32 went straight to emb_out; splits in ts for the head
                bf16* bt;
                bt = hsH; hsH = tsH; tsH = bt;
                bt = hsL; hsL = tsL; tsL = bt;
                break;
            }
        } else {
            int total4 = N_NODES * H / 4;
            bn_apply_relu_kernel<<<(total4 + 255) / 256, 256>>>(tf, tsH, tsL);
        }
        float* ft = hf; hf = tf; tf = ft;
        bf16* bt;
        bt = hsH; hsH = tsH; tsH = bt;
        bt = hsL; hsL = tsL; tsL = bt;
    }

    // ---- MLP head (embeddings already written to emb_out by last skip GEMM) ----
    run_gemm(hsH, hsL, W1H, W1L, H,
             nullptr, nullptr, nullptr, nullptr, 0,
             b1, t1f, t1f, t1H, t1L, N_NODES, H / 2, /*bias|relu*/5);
    run_gemm(t1H, t1L, W2H, W2L, H / 2,
             nullptr, nullptr, nullptr, nullptr, 0,
             b2, tf, tf, nullptr, nullptr, N_NODES, H / 4, /*bias|relu*/5);
    head3_kernel<<<(N_NODES + 255) / 256, 256>>>(tf, W3, b3, logits_out);
}